// round 2
// baseline (speedup 1.0000x reference)
#include <cuda_runtime.h>

// ---------------- problem constants ----------------
#define NL   6
#define HD   1024
#define AD   1024
#define FI   4096
#define NB   4
#define NT   2048
#define NTOK (NB * NT)   // 8192 tokens

// ---------------- persistent scratch (device globals; no allocation) ------
__device__ float g_h  [NTOK * HD];
__device__ float g_x  [NTOK * HD];
__device__ float g_xk [NTOK * HD];
__device__ float g_xv [NTOK * HD];
__device__ float g_xr [NTOK * HD];
__device__ float g_k  [NTOK * AD];
__device__ float g_v  [NTOK * AD];
__device__ float g_r  [NTOK * AD];
__device__ float g_y  [NTOK * AD];
__device__ float g_ffk[NTOK * FI];

// ---------------- block reduction (256 threads) ----------------
__device__ __forceinline__ float blkSum(float v) {
#pragma unroll
    for (int o = 16; o; o >>= 1) v += __shfl_xor_sync(0xffffffffu, v, o);
    __shared__ float sh[8];
    int w = threadIdx.x >> 5, l = threadIdx.x & 31;
    __syncthreads();                 // protect reuse across calls
    if (l == 0) sh[w] = v;
    __syncthreads();
    float s = 0.f;
#pragma unroll
    for (int i = 0; i < 8; i++) s += sh[i];
    return s;
}

// ---------------- layernorm: one block per token, 256 thr, H=1024 --------
__device__ __forceinline__ void ln_body(const float* __restrict__ row,
                                        const float* __restrict__ w,
                                        const float* __restrict__ b,
                                        float* __restrict__ outrow) {
    int t = threadIdx.x;
    float4 v = ((const float4*)row)[t];
    float s = blkSum(v.x + v.y + v.z + v.w);
    float mu = s * (1.f / HD);
    float dx = v.x - mu, dy = v.y - mu, dz = v.z - mu, dw = v.w - mu;
    float sq = blkSum(dx * dx + dy * dy + dz * dz + dw * dw);
    float rstd = rsqrtf(sq * (1.f / HD) + 1e-5f);
    float4 wv = ((const float4*)w)[t];
    float4 bv = ((const float4*)b)[t];
    float4 o;
    o.x = dx * rstd * wv.x + bv.x;
    o.y = dy * rstd * wv.y + bv.y;
    o.z = dz * rstd * wv.z + bv.z;
    o.w = dw * rstd * wv.w + bv.w;
    ((float4*)outrow)[t] = o;
}

__global__ void ln_kernel(const float* __restrict__ in, const float* __restrict__ w,
                          const float* __restrict__ b, float* __restrict__ out) {
    size_t n = blockIdx.x;
    ln_body(in + n * HD, w, b, out + n * HD);
}

__global__ void embed_ln_kernel(const int* __restrict__ ids, const float* __restrict__ emb,
                                const float* __restrict__ w, const float* __restrict__ b,
                                float* __restrict__ out) {
    size_t n = blockIdx.x;
    size_t idx = (size_t)ids[n];
    ln_body(emb + idx * HD, w, b, out + n * HD);
}

// ---------------- token-shift mixes ----------------
__global__ void mix3_kernel(const float* __restrict__ x,
                            const float* __restrict__ mk, const float* __restrict__ mv,
                            const float* __restrict__ mr,
                            float* __restrict__ xk, float* __restrict__ xv,
                            float* __restrict__ xr) {
    int i = blockIdx.x * 256 + threadIdx.x;      // over NTOK*HD
    int h = i & (HD - 1);
    int n = i >> 10;
    int t = n & (NT - 1);
    float cur = x[i];
    float prev = t ? x[i - HD] : 0.f;
    float a;
    a = mk[h]; xk[i] = a * cur + (1.f - a) * prev;
    a = mv[h]; xv[i] = a * cur + (1.f - a) * prev;
    a = mr[h]; xr[i] = a * cur + (1.f - a) * prev;
}

__global__ void mix2_kernel(const float* __restrict__ x,
                            const float* __restrict__ mk, const float* __restrict__ mr,
                            float* __restrict__ xk, float* __restrict__ xr) {
    int i = blockIdx.x * 256 + threadIdx.x;
    int h = i & (HD - 1);
    int n = i >> 10;
    int t = n & (NT - 1);
    float cur = x[i];
    float prev = t ? x[i - HD] : 0.f;
    float a;
    a = mk[h]; xk[i] = a * cur + (1.f - a) * prev;
    a = mr[h]; xr[i] = a * cur + (1.f - a) * prev;
}

// ---------------- SGEMM:  C[n,m] (+)= epi( sum_k X[n,k]*W[m,k] ) ---------
// 128x128 block tile, BK=16, 256 threads, 8x8 per thread.
// EPI: 0 store, 1 sigmoid, 2 relu^2, 3 accumulate (+=), 4 C += aux*val
template <int EPI>
__global__ __launch_bounds__(256, 2) void sgemm_nt(
    const float* __restrict__ X, const float* __restrict__ W,
    float* __restrict__ C, const float* __restrict__ aux,
    int M, int K) {
    __shared__ float Xs[16][128];
    __shared__ float Ws[16][128];
    const int tid = threadIdx.x;
    const int mB = blockIdx.x << 7;
    const int nB = blockIdx.y << 7;
    const int lr = tid >> 2;            // 0..63
    const int lk = (tid & 3) << 2;      // 0,4,8,12
    const float* Xg = X + (size_t)(nB + lr) * K + lk;
    const float* Wg = W + (size_t)(mB + lr) * K + lk;
    const size_t rowStep = (size_t)64 * K;
    const int tx = tid & 15, ty = tid >> 4;

    float c[8][8];
#pragma unroll
    for (int i = 0; i < 8; i++)
#pragma unroll
        for (int j = 0; j < 8; j++) c[i][j] = 0.f;

    for (int k0 = 0; k0 < K; k0 += 16) {
        float4 x0 = *(const float4*)(Xg + k0);
        float4 x1 = *(const float4*)(Xg + rowStep + k0);
        float4 w0 = *(const float4*)(Wg + k0);
        float4 w1 = *(const float4*)(Wg + rowStep + k0);
        __syncthreads();
        Xs[lk + 0][lr]      = x0.x; Xs[lk + 1][lr]      = x0.y;
        Xs[lk + 2][lr]      = x0.z; Xs[lk + 3][lr]      = x0.w;
        Xs[lk + 0][lr + 64] = x1.x; Xs[lk + 1][lr + 64] = x1.y;
        Xs[lk + 2][lr + 64] = x1.z; Xs[lk + 3][lr + 64] = x1.w;
        Ws[lk + 0][lr]      = w0.x; Ws[lk + 1][lr]      = w0.y;
        Ws[lk + 2][lr]      = w0.z; Ws[lk + 3][lr]      = w0.w;
        Ws[lk + 0][lr + 64] = w1.x; Ws[lk + 1][lr + 64] = w1.y;
        Ws[lk + 2][lr + 64] = w1.z; Ws[lk + 3][lr + 64] = w1.w;
        __syncthreads();
#pragma unroll
        for (int kk = 0; kk < 16; kk++) {
            float a[8], bb[8];
            *(float4*)&a[0]  = *(const float4*)&Xs[kk][ty << 3];
            *(float4*)&a[4]  = *(const float4*)&Xs[kk][(ty << 3) + 4];
            *(float4*)&bb[0] = *(const float4*)&Ws[kk][tx << 3];
            *(float4*)&bb[4] = *(const float4*)&Ws[kk][(tx << 3) + 4];
#pragma unroll
            for (int i = 0; i < 8; i++)
#pragma unroll
                for (int j = 0; j < 8; j++)
                    c[i][j] = fmaf(a[i], bb[j], c[i][j]);
        }
    }

#pragma unroll
    for (int i = 0; i < 8; i++) {
        int n = nB + (ty << 3) + i;
        float* Cr = C + (size_t)n * M + mB + (tx << 3);
#pragma unroll
        for (int j = 0; j < 8; j++) {
            float v = c[i][j];
            if (EPI == 0) {
                Cr[j] = v;
            } else if (EPI == 1) {
                Cr[j] = 1.f / (1.f + __expf(-v));
            } else if (EPI == 2) {
                float t2 = fmaxf(v, 0.f);
                Cr[j] = t2 * t2;
            } else if (EPI == 3) {
                Cr[j] += v;
            } else {
                const float* Ar = aux + (size_t)n * M + mB + (tx << 3);
                Cr[j] = fmaf(Ar[j], v, Cr[j]);
            }
        }
    }
}

// ---------------- WKV scan: one thread per (batch, channel) lane ---------
// Writes y = sigmoid_r * wkv_out  (r already has sigmoid applied)
__global__ void wkv_kernel(const float* __restrict__ tf, const float* __restrict__ td,
                           const float* __restrict__ k, const float* __restrict__ v,
                           const float* __restrict__ r, float* __restrict__ y) {
    int lane = blockIdx.x * 256 + threadIdx.x;   // 0..NB*AD-1
    int b = lane >> 10;
    int a = lane & (AD - 1);
    float u = tf[a];
    float w = -__expf(td[a]);
    float aa = 0.f, bb = 0.f, pp = -1e38f;
    size_t base = ((size_t)b * NT) * AD + a;
    // software-pipelined loads
    float kt = k[base], vt = v[base], rt = r[base];
    for (int t = 0; t < NT; t++) {
        size_t off = base + (size_t)t * AD;
        float kn = 0.f, vn = 0.f, rn = 0.f;
        if (t + 1 < NT) {
            kn = k[off + AD]; vn = v[off + AD]; rn = r[off + AD];
        }
        float uk = u + kt;
        float q  = fmaxf(pp, uk);
        float e1 = __expf(uk - q);
        float e2 = __expf(pp - q);
        float num = fmaf(aa, e2, e1 * vt);
        float den = fmaf(bb, e2, e1);
        y[off] = rt * (num / den);
        float pw = pp + w;
        float q2 = fmaxf(pw, kt);
        float s1 = __expf(pw - q2);
        float s2 = __expf(kt - q2);
        aa = fmaf(s1, aa, s2 * vt);
        bb = fmaf(s1, bb, s2);
        pp = q2;
        kt = kn; vt = vn; rt = rn;
    }
}

// ---------------- orchestration ----------------
extern "C" void kernel_launch(void* const* d_in, const int* in_sizes, int n_in,
                              void* d_out, int out_size) {
    const int*   ids   = (const int*)d_in[0];
    const float* emb   = (const float*)d_in[1];
    const float* prew  = (const float*)d_in[2];
    const float* preb  = (const float*)d_in[3];
    const float* postw = (const float*)d_in[4];
    const float* postb = (const float*)d_in[5];
    const float* ln1w  = (const float*)d_in[6];
    const float* ln1b  = (const float*)d_in[7];
    const float* ln2w  = (const float*)d_in[8];
    const float* ln2b  = (const float*)d_in[9];
    const float* mxk   = (const float*)d_in[10];
    const float* mxv   = (const float*)d_in[11];
    const float* mxr   = (const float*)d_in[12];
    const float* wk    = (const float*)d_in[13];
    const float* wv    = (const float*)d_in[14];
    const float* wr    = (const float*)d_in[15];
    const float* wo    = (const float*)d_in[16];
    const float* tdec  = (const float*)d_in[17];
    const float* tfir  = (const float*)d_in[18];
    const float* fmk   = (const float*)d_in[19];
    const float* fmr   = (const float*)d_in[20];
    const float* fwk   = (const float*)d_in[21];
    const float* fwr   = (const float*)d_in[22];
    const float* fwv   = (const float*)d_in[23];
    float* out = (float*)d_out;

    void* p;
    cudaGetSymbolAddress(&p, g_h);   float* h   = (float*)p;
    cudaGetSymbolAddress(&p, g_x);   float* x   = (float*)p;
    cudaGetSymbolAddress(&p, g_xk);  float* xk  = (float*)p;
    cudaGetSymbolAddress(&p, g_xv);  float* xv  = (float*)p;
    cudaGetSymbolAddress(&p, g_xr);  float* xr  = (float*)p;
    cudaGetSymbolAddress(&p, g_k);   float* kb  = (float*)p;
    cudaGetSymbolAddress(&p, g_v);   float* vb  = (float*)p;
    cudaGetSymbolAddress(&p, g_r);   float* rb  = (float*)p;
    cudaGetSymbolAddress(&p, g_y);   float* yb  = (float*)p;
    cudaGetSymbolAddress(&p, g_ffk); float* ffk = (float*)p;

    const dim3 gH(HD / 128, NTOK / 128);   // (8, 64)
    const dim3 gI(FI / 128, NTOK / 128);   // (32, 64)
    const int  eg = NTOK * HD / 256;       // elementwise grid

    embed_ln_kernel<<<NTOK, 256>>>(ids, emb, prew, preb, h);

    for (int i = 0; i < NL; i++) {
        // ---- attention / time mix ----
        ln_kernel<<<NTOK, 256>>>(h, ln1w + i * HD, ln1b + i * HD, x);
        mix3_kernel<<<eg, 256>>>(x, mxk + i * HD, mxv + i * HD, mxr + i * HD,
                                 xk, xv, xr);
        sgemm_nt<0><<<gH, 256>>>(xk, wk + (size_t)i * AD * HD, kb, nullptr, AD, HD);
        sgemm_nt<0><<<gH, 256>>>(xv, wv + (size_t)i * AD * HD, vb, nullptr, AD, HD);
        sgemm_nt<1><<<gH, 256>>>(xr, wr + (size_t)i * AD * HD, rb, nullptr, AD, HD);
        wkv_kernel<<<NB * AD / 256, 256>>>(tfir + i * AD, tdec + i * AD,
                                           kb, vb, rb, yb);
        sgemm_nt<3><<<gH, 256>>>(yb, wo + (size_t)i * HD * AD, h, nullptr, HD, AD);
        // ---- ffn / channel mix ----
        ln_kernel<<<NTOK, 256>>>(h, ln2w + i * HD, ln2b + i * HD, x);
        mix2_kernel<<<eg, 256>>>(x, fmk + i * HD, fmr + i * HD, xk, xr);
        sgemm_nt<2><<<gI, 256>>>(xk, fwk + (size_t)i * FI * HD, ffk, nullptr, FI, HD);
        sgemm_nt<1><<<gH, 256>>>(xr, fwr + (size_t)i * HD * HD, rb, nullptr, HD, HD);
        sgemm_nt<4><<<gH, 256>>>(ffk, fwv + (size_t)i * HD * FI, h, rb, HD, FI);
    }

    ln_kernel<<<NTOK, 256>>>(h, postw, postb, out);
}

// round 3
// speedup vs baseline: 1.0043x; 1.0043x over previous
#include <cuda_runtime.h>

// ---------------- problem constants ----------------
#define NL   6
#define HD   1024
#define AD   1024
#define FI   4096
#define NB   4
#define NT   2048
#define NTOK (NB * NT)   // 8192 tokens

// ---------------- persistent scratch (device globals; no allocation) ------
__device__ float g_h  [NTOK * HD];
__device__ float g_x  [NTOK * HD];
__device__ float g_xk [NTOK * HD];
__device__ float g_xv [NTOK * HD];
__device__ float g_xr [NTOK * HD];
__device__ float g_k  [NTOK * AD];
__device__ float g_v  [NTOK * AD];
__device__ float g_r  [NTOK * AD];
__device__ float g_y  [NTOK * AD];
__device__ float g_ffk[NTOK * FI];

// ---------------- block reduction (256 threads) ----------------
__device__ __forceinline__ float blkSum(float v) {
#pragma unroll
    for (int o = 16; o; o >>= 1) v += __shfl_xor_sync(0xffffffffu, v, o);
    __shared__ float sh[8];
    int w = threadIdx.x >> 5, l = threadIdx.x & 31;
    __syncthreads();                 // protect reuse across calls
    if (l == 0) sh[w] = v;
    __syncthreads();
    float s = 0.f;
#pragma unroll
    for (int i = 0; i < 8; i++) s += sh[i];
    return s;
}

// ---------------- layernorm: one block per token, 256 thr, H=1024 --------
__device__ __forceinline__ void ln_body(const float* __restrict__ row,
                                        const float* __restrict__ w,
                                        const float* __restrict__ b,
                                        float* __restrict__ outrow) {
    int t = threadIdx.x;
    float4 v = ((const float4*)row)[t];
    float s = blkSum(v.x + v.y + v.z + v.w);
    float mu = s * (1.f / HD);
    float dx = v.x - mu, dy = v.y - mu, dz = v.z - mu, dw = v.w - mu;
    float sq = blkSum(dx * dx + dy * dy + dz * dz + dw * dw);
    float rstd = rsqrtf(sq * (1.f / HD) + 1e-5f);
    float4 wv = ((const float4*)w)[t];
    float4 bv = ((const float4*)b)[t];
    float4 o;
    o.x = dx * rstd * wv.x + bv.x;
    o.y = dy * rstd * wv.y + bv.y;
    o.z = dz * rstd * wv.z + bv.z;
    o.w = dw * rstd * wv.w + bv.w;
    ((float4*)outrow)[t] = o;
}

__global__ void ln_kernel(const float* __restrict__ in, const float* __restrict__ w,
                          const float* __restrict__ b, float* __restrict__ out) {
    size_t n = blockIdx.x;
    ln_body(in + n * HD, w, b, out + n * HD);
}

__global__ void embed_ln_kernel(const int* __restrict__ ids, const float* __restrict__ emb,
                                const float* __restrict__ w, const float* __restrict__ b,
                                float* __restrict__ out) {
    size_t n = blockIdx.x;
    size_t idx = (size_t)ids[n];
    ln_body(emb + idx * HD, w, b, out + n * HD);
}

// ---------------- token-shift mixes ----------------
__global__ void mix3_kernel(const float* __restrict__ x,
                            const float* __restrict__ mk, const float* __restrict__ mv,
                            const float* __restrict__ mr,
                            float* __restrict__ xk, float* __restrict__ xv,
                            float* __restrict__ xr) {
    int i = blockIdx.x * 256 + threadIdx.x;      // over NTOK*HD
    int h = i & (HD - 1);
    int n = i >> 10;
    int t = n & (NT - 1);
    float cur = x[i];
    float prev = t ? x[i - HD] : 0.f;
    float a;
    a = mk[h]; xk[i] = a * cur + (1.f - a) * prev;
    a = mv[h]; xv[i] = a * cur + (1.f - a) * prev;
    a = mr[h]; xr[i] = a * cur + (1.f - a) * prev;
}

__global__ void mix2_kernel(const float* __restrict__ x,
                            const float* __restrict__ mk, const float* __restrict__ mr,
                            float* __restrict__ xk, float* __restrict__ xr) {
    int i = blockIdx.x * 256 + threadIdx.x;
    int h = i & (HD - 1);
    int n = i >> 10;
    int t = n & (NT - 1);
    float cur = x[i];
    float prev = t ? x[i - HD] : 0.f;
    float a;
    a = mk[h]; xk[i] = a * cur + (1.f - a) * prev;
    a = mr[h]; xr[i] = a * cur + (1.f - a) * prev;
}

// ---------------- SGEMM:  C[n,m] (+)= epi( sum_k X[n,k]*W[m,k] ) ---------
// 128x128 block tile, BK=16, 256 threads, 8x8 per thread.
// EPI: 0 store, 1 sigmoid, 2 relu^2, 3 accumulate (+=), 4 C += aux*val
template <int EPI>
__global__ __launch_bounds__(256, 2) void sgemm_nt(
    const float* __restrict__ X, const float* __restrict__ W,
    float* __restrict__ C, const float* __restrict__ aux,
    int M, int K) {
    __shared__ float Xs[16][128];
    __shared__ float Ws[16][128];
    const int tid = threadIdx.x;
    const int mB = blockIdx.x << 7;
    const int nB = blockIdx.y << 7;
    const int lr = tid >> 2;            // 0..63
    const int lk = (tid & 3) << 2;      // 0,4,8,12
    const float* Xg = X + (size_t)(nB + lr) * K + lk;
    const float* Wg = W + (size_t)(mB + lr) * K + lk;
    const size_t rowStep = (size_t)64 * K;
    const int tx = tid & 15, ty = tid >> 4;

    float c[8][8];
#pragma unroll
    for (int i = 0; i < 8; i++)
#pragma unroll
        for (int j = 0; j < 8; j++) c[i][j] = 0.f;

    for (int k0 = 0; k0 < K; k0 += 16) {
        float4 x0 = *(const float4*)(Xg + k0);
        float4 x1 = *(const float4*)(Xg + rowStep + k0);
        float4 w0 = *(const float4*)(Wg + k0);
        float4 w1 = *(const float4*)(Wg + rowStep + k0);
        __syncthreads();
        Xs[lk + 0][lr]      = x0.x; Xs[lk + 1][lr]      = x0.y;
        Xs[lk + 2][lr]      = x0.z; Xs[lk + 3][lr]      = x0.w;
        Xs[lk + 0][lr + 64] = x1.x; Xs[lk + 1][lr + 64] = x1.y;
        Xs[lk + 2][lr + 64] = x1.z; Xs[lk + 3][lr + 64] = x1.w;
        Ws[lk + 0][lr]      = w0.x; Ws[lk + 1][lr]      = w0.y;
        Ws[lk + 2][lr]      = w0.z; Ws[lk + 3][lr]      = w0.w;
        Ws[lk + 0][lr + 64] = w1.x; Ws[lk + 1][lr + 64] = w1.y;
        Ws[lk + 2][lr + 64] = w1.z; Ws[lk + 3][lr + 64] = w1.w;
        __syncthreads();
#pragma unroll
        for (int kk = 0; kk < 16; kk++) {
            float a[8], bb[8];
            *(float4*)&a[0]  = *(const float4*)&Xs[kk][ty << 3];
            *(float4*)&a[4]  = *(const float4*)&Xs[kk][(ty << 3) + 4];
            *(float4*)&bb[0] = *(const float4*)&Ws[kk][tx << 3];
            *(float4*)&bb[4] = *(const float4*)&Ws[kk][(tx << 3) + 4];
#pragma unroll
            for (int i = 0; i < 8; i++)
#pragma unroll
                for (int j = 0; j < 8; j++)
                    c[i][j] = fmaf(a[i], bb[j], c[i][j]);
        }
    }

#pragma unroll
    for (int i = 0; i < 8; i++) {
        int n = nB + (ty << 3) + i;
        float* Cr = C + (size_t)n * M + mB + (tx << 3);
#pragma unroll
        for (int j = 0; j < 8; j++) {
            float v = c[i][j];
            if (EPI == 0) {
                Cr[j] = v;
            } else if (EPI == 1) {
                Cr[j] = 1.f / (1.f + __expf(-v));
            } else if (EPI == 2) {
                float t2 = fmaxf(v, 0.f);
                Cr[j] = t2 * t2;
            } else if (EPI == 3) {
                Cr[j] += v;
            } else {
                const float* Ar = aux + (size_t)n * M + mB + (tx << 3);
                Cr[j] = fmaf(Ar[j], v, Cr[j]);
            }
        }
    }
}

// ---------------- WKV scan: one thread per (batch, channel) lane ---------
// Writes y = sigmoid_r * wkv_out  (r already has sigmoid applied)
__global__ void wkv_kernel(const float* __restrict__ tf, const float* __restrict__ td,
                           const float* __restrict__ k, const float* __restrict__ v,
                           const float* __restrict__ r, float* __restrict__ y) {
    int lane = blockIdx.x * 256 + threadIdx.x;   // 0..NB*AD-1
    int b = lane >> 10;
    int a = lane & (AD - 1);
    float u = tf[a];
    float w = -__expf(td[a]);
    float aa = 0.f, bb = 0.f, pp = -1e38f;
    size_t base = ((size_t)b * NT) * AD + a;
    // software-pipelined loads
    float kt = k[base], vt = v[base], rt = r[base];
    for (int t = 0; t < NT; t++) {
        size_t off = base + (size_t)t * AD;
        float kn = 0.f, vn = 0.f, rn = 0.f;
        if (t + 1 < NT) {
            kn = k[off + AD]; vn = v[off + AD]; rn = r[off + AD];
        }
        float uk = u + kt;
        float q  = fmaxf(pp, uk);
        float e1 = __expf(uk - q);
        float e2 = __expf(pp - q);
        float num = fmaf(aa, e2, e1 * vt);
        float den = fmaf(bb, e2, e1);
        y[off] = rt * (num / den);
        float pw = pp + w;
        float q2 = fmaxf(pw, kt);
        float s1 = __expf(pw - q2);
        float s2 = __expf(kt - q2);
        aa = fmaf(s1, aa, s2 * vt);
        bb = fmaf(s1, bb, s2);
        pp = q2;
        kt = kn; vt = vn; rt = rn;
    }
}

// ---------------- orchestration ----------------
extern "C" void kernel_launch(void* const* d_in, const int* in_sizes, int n_in,
                              void* d_out, int out_size) {
    const int*   ids   = (const int*)d_in[0];
    const float* emb   = (const float*)d_in[1];
    const float* prew  = (const float*)d_in[2];
    const float* preb  = (const float*)d_in[3];
    const float* postw = (const float*)d_in[4];
    const float* postb = (const float*)d_in[5];
    const float* ln1w  = (const float*)d_in[6];
    const float* ln1b  = (const float*)d_in[7];
    const float* ln2w  = (const float*)d_in[8];
    const float* ln2b  = (const float*)d_in[9];
    const float* mxk   = (const float*)d_in[10];
    const float* mxv   = (const float*)d_in[11];
    const float* mxr   = (const float*)d_in[12];
    const float* wk    = (const float*)d_in[13];
    const float* wv    = (const float*)d_in[14];
    const float* wr    = (const float*)d_in[15];
    const float* wo    = (const float*)d_in[16];
    const float* tdec  = (const float*)d_in[17];
    const float* tfir  = (const float*)d_in[18];
    const float* fmk   = (const float*)d_in[19];
    const float* fmr   = (const float*)d_in[20];
    const float* fwk   = (const float*)d_in[21];
    const float* fwr   = (const float*)d_in[22];
    const float* fwv   = (const float*)d_in[23];
    float* out = (float*)d_out;

    void* p;
    cudaGetSymbolAddress(&p, g_h);   float* h   = (float*)p;
    cudaGetSymbolAddress(&p, g_x);   float* x   = (float*)p;
    cudaGetSymbolAddress(&p, g_xk);  float* xk  = (float*)p;
    cudaGetSymbolAddress(&p, g_xv);  float* xv  = (float*)p;
    cudaGetSymbolAddress(&p, g_xr);  float* xr  = (float*)p;
    cudaGetSymbolAddress(&p, g_k);   float* kb  = (float*)p;
    cudaGetSymbolAddress(&p, g_v);   float* vb  = (float*)p;
    cudaGetSymbolAddress(&p, g_r);   float* rb  = (float*)p;
    cudaGetSymbolAddress(&p, g_y);   float* yb  = (float*)p;
    cudaGetSymbolAddress(&p, g_ffk); float* ffk = (float*)p;

    const dim3 gH(HD / 128, NTOK / 128);   // (8, 64)
    const dim3 gI(FI / 128, NTOK / 128);   // (32, 64)
    const int  eg = NTOK * HD / 256;       // elementwise grid

    embed_ln_kernel<<<NTOK, 256>>>(ids, emb, prew, preb, h);

    for (int i = 0; i < NL; i++) {
        // ---- attention / time mix ----
        ln_kernel<<<NTOK, 256>>>(h, ln1w + i * HD, ln1b + i * HD, x);
        mix3_kernel<<<eg, 256>>>(x, mxk + i * HD, mxv + i * HD, mxr + i * HD,
                                 xk, xv, xr);
        sgemm_nt<0><<<gH, 256>>>(xk, wk + (size_t)i * AD * HD, kb, nullptr, AD, HD);
        sgemm_nt<0><<<gH, 256>>>(xv, wv + (size_t)i * AD * HD, vb, nullptr, AD, HD);
        sgemm_nt<1><<<gH, 256>>>(xr, wr + (size_t)i * AD * HD, rb, nullptr, AD, HD);
        wkv_kernel<<<NB * AD / 256, 256>>>(tfir + i * AD, tdec + i * AD,
                                           kb, vb, rb, yb);
        sgemm_nt<3><<<gH, 256>>>(yb, wo + (size_t)i * HD * AD, h, nullptr, HD, AD);
        // ---- ffn / channel mix ----
        ln_kernel<<<NTOK, 256>>>(h, ln2w + i * HD, ln2b + i * HD, x);
        mix2_kernel<<<eg, 256>>>(x, fmk + i * HD, fmr + i * HD, xk, xr);
        sgemm_nt<2><<<gI, 256>>>(xk, fwk + (size_t)i * FI * HD, ffk, nullptr, FI, HD);
        sgemm_nt<1><<<gH, 256>>>(xr, fwr + (size_t)i * HD * HD, rb, nullptr, HD, HD);
        sgemm_nt<4><<<gH, 256>>>(ffk, fwv + (size_t)i * HD * FI, h, rb, HD, FI);
    }

    ln_kernel<<<NTOK, 256>>>(h, postw, postb, out);
}

// round 5
// speedup vs baseline: 2.4877x; 2.4771x over previous
#include <cuda_runtime.h>
#include <cuda_bf16.h>
#include <cstdint>

// ---------------- problem constants ----------------
#define NL    6
#define HD    1024
#define AD    1024
#define FI    4096
#define NBB   4
#define TSEQ  2048
#define NTOK  (NBB * TSEQ)     // 8192 tokens

// ---------------- GEMM tile constants ----------------
#define BM 128
#define BN 128
#define BK 64                  // bf16 elems per K tile (128B rows = SW128 atom)
#define STAGES 3
#define STAGE_BYTES 32768      // 16KB A + 16KB B
#define SMEM_SZ (STAGES * STAGE_BYTES)   // 98304

#define SWZ(o) ((o) ^ ((((uint32_t)(o)) >> 3) & 0x70))

// ---------------- persistent scratch ----------------
__device__ __align__(16) float g_h[NTOK * HD];
__device__ __align__(16) float g_x[NTOK * HD];
__device__ __align__(16) float g_k[NTOK * AD];
__device__ __align__(16) float g_v[NTOK * AD];
__device__ __align__(16) float g_r[NTOK * AD];
__device__ __align__(16) __nv_bfloat16 g_xkh[NTOK * HD], g_xkl[NTOK * HD];
__device__ __align__(16) __nv_bfloat16 g_xvh[NTOK * HD], g_xvl[NTOK * HD];
__device__ __align__(16) __nv_bfloat16 g_xrh[NTOK * HD], g_xrl[NTOK * HD];
__device__ __align__(16) __nv_bfloat16 g_yh[NTOK * AD], g_yl[NTOK * AD];
__device__ __align__(16) __nv_bfloat16 g_fkh[NTOK * FI], g_fkl[NTOK * FI];
// weight hi/lo
__device__ __align__(16) __nv_bfloat16 g_wkh[NL * AD * HD], g_wkl[NL * AD * HD];
__device__ __align__(16) __nv_bfloat16 g_wvh[NL * AD * HD], g_wvl[NL * AD * HD];
__device__ __align__(16) __nv_bfloat16 g_wrh[NL * AD * HD], g_wrl[NL * AD * HD];
__device__ __align__(16) __nv_bfloat16 g_woh[NL * HD * AD], g_wol[NL * HD * AD];
__device__ __align__(16) __nv_bfloat16 g_fwkh[NL * FI * HD], g_fwkl[NL * FI * HD];
__device__ __align__(16) __nv_bfloat16 g_fwrh[NL * HD * HD], g_fwrl[NL * HD * HD];
__device__ __align__(16) __nv_bfloat16 g_fwvh[NL * HD * FI], g_fwvl[NL * HD * FI];

// ---------------- PTX helpers (portable sm_80+ features only) ----------------
__device__ __forceinline__ uint32_t smem_u32(const void* p) {
    uint32_t a;
    asm("{ .reg .u64 t; cvta.to.shared.u64 t, %1; cvt.u32.u64 %0, t; }"
        : "=r"(a) : "l"(p));
    return a;
}

#define CPASYNC16(saddr, gptr)                                                \
    asm volatile("cp.async.cg.shared.global [%0], [%1], 16;"                  \
                 :: "r"(saddr), "l"(gptr))
#define CPCOMMIT() asm volatile("cp.async.commit_group;" ::: "memory")
#define CPWAIT1()  asm volatile("cp.async.wait_group 1;" ::: "memory")

#define LDSM4(r0, r1, r2, r3, addr)                                           \
    asm volatile("ldmatrix.sync.aligned.m8n8.x4.shared.b16 {%0,%1,%2,%3}, [%4];" \
                 : "=r"(r0), "=r"(r1), "=r"(r2), "=r"(r3) : "r"(addr))

#define MMA16816(d, a, b)                                                     \
    asm volatile("mma.sync.aligned.m16n8k16.row.col.f32.bf16.bf16.f32 "       \
                 "{%0,%1,%2,%3}, {%4,%5,%6,%7}, {%8,%9}, {%0,%1,%2,%3};"      \
                 : "+f"((d)[0]), "+f"((d)[1]), "+f"((d)[2]), "+f"((d)[3])     \
                 : "r"((a)[0]), "r"((a)[1]), "r"((a)[2]), "r"((a)[3]),        \
                   "r"((b)[0]), "r"((b)[1]))

__device__ __forceinline__ void split_bf(float v, __nv_bfloat16& h, __nv_bfloat16& l) {
    h = __float2bfloat16(v);
    l = __float2bfloat16(v - __bfloat162float(h));
}

// ================= mma.sync bf16 GEMM, 3 hi/lo segments =================
// C[n_tok, m_feat] = epi( sum_k X[n,k] * W[m,k] )
// EPI: 0 fp32 store, 1 sigmoid fp32, 2 relu^2 -> bf16 hi/lo, 3 C+=v, 4 C+=aux*v
template <int EPI>
__global__ __launch_bounds__(256)
void gemm_tc(const __nv_bfloat16* __restrict__ Ah, const __nv_bfloat16* __restrict__ Al,
             const __nv_bfloat16* __restrict__ Bh, const __nv_bfloat16* __restrict__ Bl,
             float* __restrict__ C, __nv_bfloat16* __restrict__ Ch,
             __nv_bfloat16* __restrict__ Cl, const float* __restrict__ aux,
             int Mfeat, int K) {
    extern __shared__ char smem[];
    const uint32_t sb = smem_u32(smem);
    const int tid  = threadIdx.x;
    const int lane = tid & 31;
    const int wid  = tid >> 5;
    const int wm   = wid >> 2;          // 0..1  (M warp)
    const int wn   = wid & 3;           // 0..3  (N warp)
    const int tokBase  = blockIdx.y << 7;
    const int featBase = blockIdx.x << 7;
    const int lrow  = lane & 15;
    const int lhalf = lane >> 4;
    const int ktiles = K >> 6;
    const int TT = 3 * ktiles;

    // ---- per-thread load mapping: 4 x 16B chunks of one row half for A and B
    const int ldrow = tid >> 1;          // 0..127
    const int ldcb  = (tid & 1) << 2;    // chunk base 0 or 4
    const size_t aoff = (size_t)(tokBase + ldrow) * K;
    const size_t boff = (size_t)(featBase + ldrow) * K;
    uint32_t smoff[4];
#pragma unroll
    for (int j = 0; j < 4; j++)
        smoff[j] = SWZ(ldrow * 128 + (ldcb + j) * 16);

    auto issue = [&](int tt) {
        const int seg  = tt / ktiles;
        const int koff = (tt - seg * ktiles) << 6;
        const __nv_bfloat16* Ap = (seg == 1) ? Al : Ah;
        const __nv_bfloat16* Bp = (seg == 2) ? Bl : Bh;
        const uint32_t st = sb + (uint32_t)(tt % STAGES) * STAGE_BYTES;
        const __nv_bfloat16* ag = Ap + aoff + koff + ldcb * 8;
        const __nv_bfloat16* bg = Bp + boff + koff + ldcb * 8;
#pragma unroll
        for (int j = 0; j < 4; j++) {
            CPASYNC16(st + smoff[j], (const void*)__cvta_generic_to_global(ag + j * 8));
            CPASYNC16(st + 16384u + smoff[j], (const void*)__cvta_generic_to_global(bg + j * 8));
        }
    };

    float c[4][4][4];
#pragma unroll
    for (int i = 0; i < 4; i++)
#pragma unroll
        for (int j = 0; j < 4; j++)
#pragma unroll
            for (int q = 0; q < 4; q++) c[i][j][q] = 0.f;

    issue(0); CPCOMMIT();
    issue(1); CPCOMMIT();

    for (int tt = 0; tt < TT; tt++) {
        CPWAIT1();
        __syncthreads();
        if (tt + 2 < TT) issue(tt + 2);
        CPCOMMIT();

        const uint32_t Ab = sb + (uint32_t)(tt % STAGES) * STAGE_BYTES;
        const uint32_t Bb = Ab + 16384u;
#pragma unroll
        for (int ks = 0; ks < 4; ks++) {
            const uint32_t kcol = (uint32_t)(ks * 2 + lhalf) * 16;
            uint32_t a[4][4];
#pragma unroll
            for (int mf = 0; mf < 4; mf++) {
                uint32_t ad = Ab + SWZ((uint32_t)(wm * 64 + mf * 16 + lrow) * 128 + kcol);
                LDSM4(a[mf][0], a[mf][1], a[mf][2], a[mf][3], ad);
            }
            uint32_t b[4][2];
#pragma unroll
            for (int g = 0; g < 2; g++) {
                uint32_t r0, r1, r2, r3;
                uint32_t bd = Bb + SWZ((uint32_t)(wn * 32 + g * 16 + lrow) * 128 + kcol);
                LDSM4(r0, r1, r2, r3, bd);
                b[2 * g][0] = r0;     b[2 * g][1] = r2;
                b[2 * g + 1][0] = r1; b[2 * g + 1][1] = r3;
            }
#pragma unroll
            for (int mf = 0; mf < 4; mf++)
#pragma unroll
                for (int nf = 0; nf < 4; nf++)
                    MMA16816(c[mf][nf], a[mf], b[nf]);
        }
    }

    // ---------------- epilogue (register accumulators) ----------------
    const int rbase = tokBase + wm * 64 + (lane >> 2);
    const int cbase = featBase + wn * 32 + (lane & 3) * 2;
#pragma unroll
    for (int mf = 0; mf < 4; mf++) {
#pragma unroll
        for (int nf = 0; nf < 4; nf++) {
            const int row = rbase + mf * 16;
            const int col = cbase + nf * 8;
#pragma unroll
            for (int half = 0; half < 2; half++) {
                const int r = row + half * 8;
                float vx = c[mf][nf][half * 2 + 0];
                float vy = c[mf][nf][half * 2 + 1];
                const size_t idx = (size_t)r * Mfeat + col;
                if (EPI == 0) {
                    *(float2*)(C + idx) = make_float2(vx, vy);
                } else if (EPI == 1) {
                    vx = 1.f / (1.f + __expf(-vx));
                    vy = 1.f / (1.f + __expf(-vy));
                    *(float2*)(C + idx) = make_float2(vx, vy);
                } else if (EPI == 2) {
                    vx = fmaxf(vx, 0.f); vx = vx * vx;
                    vy = fmaxf(vy, 0.f); vy = vy * vy;
                    __nv_bfloat16 hx, lx, hy, ly;
                    split_bf(vx, hx, lx);
                    split_bf(vy, hy, ly);
                    *(__nv_bfloat162*)(Ch + idx) = __nv_bfloat162(hx, hy);
                    *(__nv_bfloat162*)(Cl + idx) = __nv_bfloat162(lx, ly);
                } else if (EPI == 3) {
                    float2 cur = *(float2*)(C + idx);
                    cur.x += vx; cur.y += vy;
                    *(float2*)(C + idx) = cur;
                } else {
                    float2 cur = *(float2*)(C + idx);
                    float2 a2 = *(const float2*)(aux + idx);
                    cur.x = fmaf(a2.x, vx, cur.x);
                    cur.y = fmaf(a2.y, vy, cur.y);
                    *(float2*)(C + idx) = cur;
                }
            }
        }
    }
}

// ---------------- block reduction / layernorm ----------------
__device__ __forceinline__ float blkSum(float v) {
#pragma unroll
    for (int o = 16; o; o >>= 1) v += __shfl_xor_sync(0xffffffffu, v, o);
    __shared__ float sh[8];
    int w = threadIdx.x >> 5, l = threadIdx.x & 31;
    __syncthreads();
    if (l == 0) sh[w] = v;
    __syncthreads();
    float s = 0.f;
#pragma unroll
    for (int i = 0; i < 8; i++) s += sh[i];
    return s;
}

__device__ __forceinline__ void ln_body(const float* __restrict__ row,
                                        const float* __restrict__ w,
                                        const float* __restrict__ b,
                                        float* __restrict__ outrow) {
    int t = threadIdx.x;
    float4 v = ((const float4*)row)[t];
    float s = blkSum(v.x + v.y + v.z + v.w);
    float mu = s * (1.f / HD);
    float dx = v.x - mu, dy = v.y - mu, dz = v.z - mu, dw = v.w - mu;
    float sq = blkSum(dx * dx + dy * dy + dz * dz + dw * dw);
    float rstd = rsqrtf(sq * (1.f / HD) + 1e-5f);
    float4 wv = ((const float4*)w)[t];
    float4 bv = ((const float4*)b)[t];
    float4 o;
    o.x = dx * rstd * wv.x + bv.x;
    o.y = dy * rstd * wv.y + bv.y;
    o.z = dz * rstd * wv.z + bv.z;
    o.w = dw * rstd * wv.w + bv.w;
    ((float4*)outrow)[t] = o;
}

__global__ void ln_kernel(const float* __restrict__ in, const float* __restrict__ w,
                          const float* __restrict__ b, float* __restrict__ out) {
    size_t n = blockIdx.x;
    ln_body(in + n * HD, w, b, out + n * HD);
}

__global__ void embed_ln_kernel(const int* __restrict__ ids, const float* __restrict__ emb,
                                const float* __restrict__ w, const float* __restrict__ b,
                                float* __restrict__ out) {
    size_t n = blockIdx.x;
    size_t idx = (size_t)ids[n];
    ln_body(emb + idx * HD, w, b, out + n * HD);
}

// ---------------- token-shift mixes (emit bf16 hi/lo) ----------------
__global__ void mix3_kernel(const float* __restrict__ x,
                            const float* __restrict__ mk, const float* __restrict__ mv,
                            const float* __restrict__ mr,
                            __nv_bfloat16* __restrict__ xkh, __nv_bfloat16* __restrict__ xkl,
                            __nv_bfloat16* __restrict__ xvh, __nv_bfloat16* __restrict__ xvl,
                            __nv_bfloat16* __restrict__ xrh, __nv_bfloat16* __restrict__ xrl) {
    int i = blockIdx.x * 256 + threadIdx.x;
    int h = i & (HD - 1);
    int n = i >> 10;
    int t = n & (TSEQ - 1);
    float cur = x[i];
    float prev = t ? x[i - HD] : 0.f;
    float a, val;
    __nv_bfloat16 hh, ll;
    a = mk[h]; val = a * cur + (1.f - a) * prev; split_bf(val, hh, ll); xkh[i] = hh; xkl[i] = ll;
    a = mv[h]; val = a * cur + (1.f - a) * prev; split_bf(val, hh, ll); xvh[i] = hh; xvl[i] = ll;
    a = mr[h]; val = a * cur + (1.f - a) * prev; split_bf(val, hh, ll); xrh[i] = hh; xrl[i] = ll;
}

__global__ void mix2_kernel(const float* __restrict__ x,
                            const float* __restrict__ mk, const float* __restrict__ mr,
                            __nv_bfloat16* __restrict__ xkh, __nv_bfloat16* __restrict__ xkl,
                            __nv_bfloat16* __restrict__ xrh, __nv_bfloat16* __restrict__ xrl) {
    int i = blockIdx.x * 256 + threadIdx.x;
    int h = i & (HD - 1);
    int n = i >> 10;
    int t = n & (TSEQ - 1);
    float cur = x[i];
    float prev = t ? x[i - HD] : 0.f;
    float a, val;
    __nv_bfloat16 hh, ll;
    a = mk[h]; val = a * cur + (1.f - a) * prev; split_bf(val, hh, ll); xkh[i] = hh; xkl[i] = ll;
    a = mr[h]; val = a * cur + (1.f - a) * prev; split_bf(val, hh, ll); xrh[i] = hh; xrl[i] = ll;
}

// ---------------- weight split fp32 -> bf16 hi/lo ----------------
__global__ void split_kernel(const float* __restrict__ src,
                             __nv_bfloat16* __restrict__ h, __nv_bfloat16* __restrict__ l,
                             int n4) {
    int i = (blockIdx.x * 256 + threadIdx.x);
    if (i >= n4) return;
    float4 v = ((const float4*)src)[i];
    __nv_bfloat16 h0, h1, h2, h3, l0, l1, l2, l3;
    split_bf(v.x, h0, l0); split_bf(v.y, h1, l1);
    split_bf(v.z, h2, l2); split_bf(v.w, h3, l3);
    __nv_bfloat162* Hp = (__nv_bfloat162*)(h + (size_t)i * 4);
    __nv_bfloat162* Lp = (__nv_bfloat162*)(l + (size_t)i * 4);
    Hp[0] = __nv_bfloat162(h0, h1); Hp[1] = __nv_bfloat162(h2, h3);
    Lp[0] = __nv_bfloat162(l0, l1); Lp[1] = __nv_bfloat162(l2, l3);
}

// ---------------- WKV scan (emits y hi/lo bf16) ----------------
__global__ void wkv_kernel(const float* __restrict__ tf, const float* __restrict__ td,
                           const float* __restrict__ k, const float* __restrict__ v,
                           const float* __restrict__ r,
                           __nv_bfloat16* __restrict__ yh, __nv_bfloat16* __restrict__ yl) {
    int laneid = blockIdx.x * 256 + threadIdx.x;
    int b = laneid >> 10;
    int a = laneid & (AD - 1);
    float u = tf[a];
    float w = -__expf(td[a]);
    float aa = 0.f, bb = 0.f, pp = -1e38f;
    size_t base = ((size_t)b * TSEQ) * AD + a;
    float kt = k[base], vt = v[base], rt = r[base];
    for (int t = 0; t < TSEQ; t++) {
        size_t off = base + (size_t)t * AD;
        float kn = 0.f, vn = 0.f, rn = 0.f;
        if (t + 1 < TSEQ) { kn = k[off + AD]; vn = v[off + AD]; rn = r[off + AD]; }
        float uk = u + kt;
        float q = fmaxf(pp, uk);
        float e1 = __expf(uk - q);
        float e2 = __expf(pp - q);
        float num = fmaf(aa, e2, e1 * vt);
        float den = fmaf(bb, e2, e1);
        float o = rt * (num / den);
        __nv_bfloat16 hh, ll;
        split_bf(o, hh, ll);
        yh[off] = hh; yl[off] = ll;
        float pw = pp + w;
        float q2 = fmaxf(pw, kt);
        float s1 = __expf(pw - q2);
        float s2 = __expf(kt - q2);
        aa = fmaf(s1, aa, s2 * vt);
        bb = fmaf(s1, bb, s2);
        pp = q2;
        kt = kn; vt = vn; rt = rn;
    }
}

// ---------------- orchestration ----------------
extern "C" void kernel_launch(void* const* d_in, const int* in_sizes, int n_in,
                              void* d_out, int out_size) {
    const int*   ids   = (const int*)d_in[0];
    const float* emb   = (const float*)d_in[1];
    const float* prew  = (const float*)d_in[2];
    const float* preb  = (const float*)d_in[3];
    const float* postw = (const float*)d_in[4];
    const float* postb = (const float*)d_in[5];
    const float* ln1w  = (const float*)d_in[6];
    const float* ln1b  = (const float*)d_in[7];
    const float* ln2w  = (const float*)d_in[8];
    const float* ln2b  = (const float*)d_in[9];
    const float* mxk   = (const float*)d_in[10];
    const float* mxv   = (const float*)d_in[11];
    const float* mxr   = (const float*)d_in[12];
    const float* wk    = (const float*)d_in[13];
    const float* wv    = (const float*)d_in[14];
    const float* wr    = (const float*)d_in[15];
    const float* wo    = (const float*)d_in[16];
    const float* tdec  = (const float*)d_in[17];
    const float* tfir  = (const float*)d_in[18];
    const float* fmk   = (const float*)d_in[19];
    const float* fmr   = (const float*)d_in[20];
    const float* fwk   = (const float*)d_in[21];
    const float* fwr   = (const float*)d_in[22];
    const float* fwv   = (const float*)d_in[23];
    float* out = (float*)d_out;

    void* p;
    cudaGetSymbolAddress(&p, g_h);    float* h  = (float*)p;
    cudaGetSymbolAddress(&p, g_x);    float* x  = (float*)p;
    cudaGetSymbolAddress(&p, g_k);    float* kb = (float*)p;
    cudaGetSymbolAddress(&p, g_v);    float* vb = (float*)p;
    cudaGetSymbolAddress(&p, g_r);    float* rb = (float*)p;
    cudaGetSymbolAddress(&p, g_xkh);  __nv_bfloat16* xkh = (__nv_bfloat16*)p;
    cudaGetSymbolAddress(&p, g_xkl);  __nv_bfloat16* xkl = (__nv_bfloat16*)p;
    cudaGetSymbolAddress(&p, g_xvh);  __nv_bfloat16* xvh = (__nv_bfloat16*)p;
    cudaGetSymbolAddress(&p, g_xvl);  __nv_bfloat16* xvl = (__nv_bfloat16*)p;
    cudaGetSymbolAddress(&p, g_xrh);  __nv_bfloat16* xrh = (__nv_bfloat16*)p;
    cudaGetSymbolAddress(&p, g_xrl);  __nv_bfloat16* xrl = (__nv_bfloat16*)p;
    cudaGetSymbolAddress(&p, g_yh);   __nv_bfloat16* yh  = (__nv_bfloat16*)p;
    cudaGetSymbolAddress(&p, g_yl);   __nv_bfloat16* yl  = (__nv_bfloat16*)p;
    cudaGetSymbolAddress(&p, g_fkh);  __nv_bfloat16* fkh = (__nv_bfloat16*)p;
    cudaGetSymbolAddress(&p, g_fkl);  __nv_bfloat16* fkl = (__nv_bfloat16*)p;
    cudaGetSymbolAddress(&p, g_wkh);  __nv_bfloat16* wkh = (__nv_bfloat16*)p;
    cudaGetSymbolAddress(&p, g_wkl);  __nv_bfloat16* wkl = (__nv_bfloat16*)p;
    cudaGetSymbolAddress(&p, g_wvh);  __nv_bfloat16* wvh = (__nv_bfloat16*)p;
    cudaGetSymbolAddress(&p, g_wvl);  __nv_bfloat16* wvl = (__nv_bfloat16*)p;
    cudaGetSymbolAddress(&p, g_wrh);  __nv_bfloat16* wrh = (__nv_bfloat16*)p;
    cudaGetSymbolAddress(&p, g_wrl);  __nv_bfloat16* wrl = (__nv_bfloat16*)p;
    cudaGetSymbolAddress(&p, g_woh);  __nv_bfloat16* woh = (__nv_bfloat16*)p;
    cudaGetSymbolAddress(&p, g_wol);  __nv_bfloat16* wol = (__nv_bfloat16*)p;
    cudaGetSymbolAddress(&p, g_fwkh); __nv_bfloat16* fwkh = (__nv_bfloat16*)p;
    cudaGetSymbolAddress(&p, g_fwkl); __nv_bfloat16* fwkl = (__nv_bfloat16*)p;
    cudaGetSymbolAddress(&p, g_fwrh); __nv_bfloat16* fwrh = (__nv_bfloat16*)p;
    cudaGetSymbolAddress(&p, g_fwrl); __nv_bfloat16* fwrl = (__nv_bfloat16*)p;
    cudaGetSymbolAddress(&p, g_fwvh); __nv_bfloat16* fwvh = (__nv_bfloat16*)p;
    cudaGetSymbolAddress(&p, g_fwvl); __nv_bfloat16* fwvl = (__nv_bfloat16*)p;

    cudaFuncSetAttribute(gemm_tc<0>, cudaFuncAttributeMaxDynamicSharedMemorySize, SMEM_SZ);
    cudaFuncSetAttribute(gemm_tc<1>, cudaFuncAttributeMaxDynamicSharedMemorySize, SMEM_SZ);
    cudaFuncSetAttribute(gemm_tc<2>, cudaFuncAttributeMaxDynamicSharedMemorySize, SMEM_SZ);
    cudaFuncSetAttribute(gemm_tc<3>, cudaFuncAttributeMaxDynamicSharedMemorySize, SMEM_SZ);
    cudaFuncSetAttribute(gemm_tc<4>, cudaFuncAttributeMaxDynamicSharedMemorySize, SMEM_SZ);

    // ---- weight splits (once per launch) ----
    const int nW  = NL * AD * HD;   // 6.29M
    const int nWI = NL * FI * HD;   // 25.17M
    split_kernel<<<nW / 1024, 256>>>(wk, wkh, wkl, nW / 4);
    split_kernel<<<nW / 1024, 256>>>(wv, wvh, wvl, nW / 4);
    split_kernel<<<nW / 1024, 256>>>(wr, wrh, wrl, nW / 4);
    split_kernel<<<nW / 1024, 256>>>(wo, woh, wol, nW / 4);
    split_kernel<<<nWI / 1024, 256>>>(fwk, fwkh, fwkl, nWI / 4);
    split_kernel<<<nW / 1024, 256>>>(fwr, fwrh, fwrl, nW / 4);
    split_kernel<<<nWI / 1024, 256>>>(fwv, fwvh, fwvl, nWI / 4);

    const dim3 gH(HD / BN, NTOK / BM);   // (8, 64)
    const dim3 gI(FI / BN, NTOK / BM);   // (32, 64)
    const int  eg = NTOK * HD / 256;

    embed_ln_kernel<<<NTOK, 256>>>(ids, emb, prew, preb, h);

    for (int i = 0; i < NL; i++) {
        const size_t oW  = (size_t)i * AD * HD;
        const size_t oWI = (size_t)i * FI * HD;
        // ---- attention / time mix ----
        ln_kernel<<<NTOK, 256>>>(h, ln1w + i * HD, ln1b + i * HD, x);
        mix3_kernel<<<eg, 256>>>(x, mxk + i * HD, mxv + i * HD, mxr + i * HD,
                                 xkh, xkl, xvh, xvl, xrh, xrl);
        gemm_tc<0><<<gH, 256, SMEM_SZ>>>(xkh, xkl, wkh + oW, wkl + oW,
                                         kb, nullptr, nullptr, nullptr, AD, HD);
        gemm_tc<0><<<gH, 256, SMEM_SZ>>>(xvh, xvl, wvh + oW, wvl + oW,
                                         vb, nullptr, nullptr, nullptr, AD, HD);
        gemm_tc<1><<<gH, 256, SMEM_SZ>>>(xrh, xrl, wrh + oW, wrl + oW,
                                         rb, nullptr, nullptr, nullptr, AD, HD);
        wkv_kernel<<<NBB * AD / 256, 256>>>(tfir + i * AD, tdec + i * AD,
                                            kb, vb, rb, yh, yl);
        gemm_tc<3><<<gH, 256, SMEM_SZ>>>(yh, yl, woh + oW, wol + oW,
                                         h, nullptr, nullptr, nullptr, HD, AD);
        // ---- ffn / channel mix ----
        ln_kernel<<<NTOK, 256>>>(h, ln2w + i * HD, ln2b + i * HD, x);
        mix2_kernel<<<eg, 256>>>(x, fmk + i * HD, fmr + i * HD, xkh, xkl, xrh, xrl);
        gemm_tc<2><<<gI, 256, SMEM_SZ>>>(xkh, xkl, fwkh + oWI, fwkl + oWI,
                                         nullptr, fkh, fkl, nullptr, FI, HD);
        gemm_tc<1><<<gH, 256, SMEM_SZ>>>(xrh, xrl, fwrh + oW, fwrl + oW,
                                         rb, nullptr, nullptr, nullptr, HD, HD);
        gemm_tc<4><<<gH, 256, SMEM_SZ>>>(fkh, fkl, fwvh + oWI, fwvl + oWI,
                                         h, nullptr, nullptr, rb, HD, FI);
    }

    ln_kernel<<<NTOK, 256>>>(h, postw, postb, out);
}